// round 1
// baseline (speedup 1.0000x reference)
#include <cuda_runtime.h>
#include <stdint.h>

#define HH 224
#define WW 224
#define STEPS 32
#define NIMG 24            // 8 * 3

// Global signed histogram per image. Zero-initialized at module load;
// finalize_kernel re-zeros it after reading, so the invariant
// "g_hist == 0 at kernel_launch entry" holds across graph replays.
__device__ int g_hist[NIMG][STEPS];

// t_k exactly as jnp.linspace(-2, 2, 32) in float32: t_k = -2 + k * fl(4/31),
// each op rounded to nearest f32. (31*fl(4/31) rounds to 4.0f, so t_31 == 2.0f.)
__device__ __forceinline__ float tval(int k) {
    const float step = 4.0f / 31.0f;   // compile-time f32 constant
    return __fadd_rn(-2.0f, __fmul_rn((float)k, step));
}

// Smallest k in [0,31] with v <= t_k; returns 32 if v > t_31 (incl. +inf).
// Exact w.r.t. float comparisons: arithmetic guess + fixup against tval().
__device__ __forceinline__ int bin_of(float v) {
    if (!(v <= tval(31))) return 32;
    if (v <= tval(0))     return 0;
    int k = (int)((v + 2.0f) * 7.75f);   // 7.75f = 31/4 exact
    k = min(max(k, 0), 31);
    while (k > 0 && v <= tval(k - 1)) --k;
    while (v > tval(k)) ++k;             // bounded: v <= t_31
    return k;
}

__global__ __launch_bounds__(256)
void ecc_hist_kernel(const float* __restrict__ x) {
    const int j   = blockIdx.x * 32 + threadIdx.x;   // 0..255, valid <= 224
    const int i   = blockIdx.y * 8  + threadIdx.y;   // valid <= 224
    const int img = blockIdx.z;
    const int tid = threadIdx.y * 32 + threadIdx.x;

    // Per-warp signed hist, 33 slots (slot 32 = trash for v > t_31 / inf).
    // Stride 33 -> bank = (warp + bin) % 32: conflict-free for distinct bins.
    __shared__ int sh[8][33];
    #pragma unroll
    for (int s = tid; s < 8 * 33; s += 256) ((int*)sh)[s] = 0;
    __syncthreads();

    if (i <= HH && j <= WW) {
        const float* __restrict__ p = x + (size_t)img * (HH * WW);
        const float INF = __int_as_float(0x7f800000);
        // 2x2 window ending at site (i,j); OOB -> +inf (T-construction padding)
        const float a = (i > 0  && j > 0 ) ? p[(i - 1) * WW + (j - 1)] : INF;
        const float b = (i > 0  && j < WW) ? p[(i - 1) * WW + j      ] : INF;
        const float c = (i < HH && j > 0 ) ? p[i * WW + (j - 1)]       : INF;
        const float d = (i < HH && j < WW) ? p[i * WW + j]             : INF;

        int* h = sh[threadIdx.y];   // blockDim.x == 32 -> warp id == threadIdx.y

        // vert = min(a,b,c,d) [+1], e_h = min(b,d) [-1],
        // e_v = min(c,d) [-1],      face = d [+1]
        const float ac = fminf(a, c);
        const float bd = fminf(b, d);
        // pair1: +vert - e_h ; cancels unless min(a,c) < min(b,d)
        if (ac < bd) {
            atomicAdd(&h[bin_of(ac)],  1);
            atomicAdd(&h[bin_of(bd)], -1);
        }
        // pair2: -e_v + face ; cancels unless c < d
        if (c < d) {
            atomicAdd(&h[bin_of(c)], -1);
            atomicAdd(&h[bin_of(d)],  1);
        }
    }
    __syncthreads();

    // Reduce 8 warp-hists -> global (only bins 0..31 matter)
    if (tid < STEPS) {
        int s = 0;
        #pragma unroll
        for (int w = 0; w < 8; ++w) s += sh[w][tid];
        if (s != 0) atomicAdd(&g_hist[img][tid], s);
    }
}

__global__ void ecc_finalize_kernel(float* __restrict__ out) {
    const int img = blockIdx.x;
    const int t   = threadIdx.x;       // 0..31
    __shared__ int s[STEPS];
    s[t] = g_hist[img][t];
    g_hist[img][t] = 0;                // restore invariant for next replay
    __syncwarp();
    int acc = 0;
    #pragma unroll
    for (int k = 0; k < STEPS; ++k)
        if (k <= t) acc += s[k];
    out[img * STEPS + t] = (float)acc;
}

extern "C" void kernel_launch(void* const* d_in, const int* in_sizes, int n_in,
                              void* d_out, int out_size) {
    const float* x = (const float*)d_in[0];
    float* out = (float*)d_out;
    (void)in_sizes; (void)n_in; (void)out_size;

    dim3 grid((WW + 32) / 32,            // 225 cols -> 8 tiles of 32
              (HH + 8) / 8,              // 225 rows -> 29 tiles of 8
              NIMG);
    dim3 block(32, 8);
    ecc_hist_kernel<<<grid, block>>>(x);
    ecc_finalize_kernel<<<NIMG, STEPS>>>(out);
}